// round 17
// baseline (speedup 1.0000x reference)
#include <cuda_runtime.h>
#include <cuda_bf16.h>

// Scalar reduction: mean over all elements of
//   term = (a<0 && b<0) ? (b - 2a)^2 : b^2
// where a = target (d_in[1]), b = source (d_in[0]).
// Derivation: fdback - a = (a<0&&b<0) ? (b-a)-a = b-2a : (a-b)-a = -b.
//
// WARP-AUTONOMOUS dynamic scheduling: each warp pulls 1024-float4 chunks
// (16KB/array) off a global atomic ticket — NO barriers in the streaming
// loop, so warps drift independently instead of advancing in block-wide
// convoys gated by the slowest warp's scoreboard. Ticket is prefetched one
// chunk ahead (lane-0 atomic + shfl) to hide ATOMG latency. Loads are
// front-batched 8-wide (4 src + 4 tgt LDG.128, lanes consecutive -> fully
// coalesced 512B/instr). Self-resetting state; graph-replay safe.

__device__ double       g_fdloss_sum;    // zero-init at load; last block resets
__device__ unsigned int g_fdloss_tick;   // wrapping ticket; self-resets
__device__ unsigned int g_fdloss_work;   // warp-chunk counter; last block resets

#define WCHUNK_F4 1024   // float4 per warp-chunk per array = 16 KB/array

// one front-batched group of 128 float4/array: lane reads idx = g0 + lane + 32k
__device__ __forceinline__ void fd_group_w(
    const float4* __restrict__ src, const float4* __restrict__ tgt, int g0,
    float& acc0, float& acc1, float& acc2, float& acc3)
{
    float4 B[4], A[4];
    #pragma unroll
    for (int k = 0; k < 4; k++) {
        B[k] = src[g0 + k * 32];
        A[k] = tgt[g0 + k * 32];
    }
    {
        float u, s;
        u = (A[0].x < 0.f && B[0].x < 0.f) ? (B[0].x - 2.f * A[0].x) : B[0].x;
        s = u * u;
        u = (A[0].y < 0.f && B[0].y < 0.f) ? (B[0].y - 2.f * A[0].y) : B[0].y;
        s += u * u;
        u = (A[0].z < 0.f && B[0].z < 0.f) ? (B[0].z - 2.f * A[0].z) : B[0].z;
        s += u * u;
        u = (A[0].w < 0.f && B[0].w < 0.f) ? (B[0].w - 2.f * A[0].w) : B[0].w;
        s += u * u;
        acc0 += s;
    }
    {
        float u, s;
        u = (A[1].x < 0.f && B[1].x < 0.f) ? (B[1].x - 2.f * A[1].x) : B[1].x;
        s = u * u;
        u = (A[1].y < 0.f && B[1].y < 0.f) ? (B[1].y - 2.f * A[1].y) : B[1].y;
        s += u * u;
        u = (A[1].z < 0.f && B[1].z < 0.f) ? (B[1].z - 2.f * A[1].z) : B[1].z;
        s += u * u;
        u = (A[1].w < 0.f && B[1].w < 0.f) ? (B[1].w - 2.f * A[1].w) : B[1].w;
        s += u * u;
        acc1 += s;
    }
    {
        float u, s;
        u = (A[2].x < 0.f && B[2].x < 0.f) ? (B[2].x - 2.f * A[2].x) : B[2].x;
        s = u * u;
        u = (A[2].y < 0.f && B[2].y < 0.f) ? (B[2].y - 2.f * A[2].y) : B[2].y;
        s += u * u;
        u = (A[2].z < 0.f && B[2].z < 0.f) ? (B[2].z - 2.f * A[2].z) : B[2].z;
        s += u * u;
        u = (A[2].w < 0.f && B[2].w < 0.f) ? (B[2].w - 2.f * A[2].w) : B[2].w;
        s += u * u;
        acc2 += s;
    }
    {
        float u, s;
        u = (A[3].x < 0.f && B[3].x < 0.f) ? (B[3].x - 2.f * A[3].x) : B[3].x;
        s = u * u;
        u = (A[3].y < 0.f && B[3].y < 0.f) ? (B[3].y - 2.f * A[3].y) : B[3].y;
        s += u * u;
        u = (A[3].z < 0.f && B[3].z < 0.f) ? (B[3].z - 2.f * A[3].z) : B[3].z;
        s += u * u;
        u = (A[3].w < 0.f && B[3].w < 0.f) ? (B[3].w - 2.f * A[3].w) : B[3].w;
        s += u * u;
        acc3 += s;
    }
}

__global__ __launch_bounds__(256) void fdloss_kernel(
    const float4* __restrict__ src,   // b
    const float4* __restrict__ tgt,   // a
    int n4,
    int nchunk_total,
    int nchunk_full,
    float* __restrict__ out,
    double inv_n)
{
    const int t    = threadIdx.x;
    const int lane = t & 31;
    const int wid  = t >> 5;

    float acc0 = 0.f, acc1 = 0.f, acc2 = 0.f, acc3 = 0.f;

    // warp-private ticket, prefetched one chunk ahead
    unsigned int cur = 0;
    if (lane == 0) cur = atomicAdd(&g_fdloss_work, 1u);
    int chunk = (int)__shfl_sync(0xFFFFFFFFu, cur, 0);

    while (chunk < nchunk_total) {
        unsigned int nxt = 0;
        if (lane == 0) nxt = atomicAdd(&g_fdloss_work, 1u);  // prefetch next

        const int base = chunk * WCHUNK_F4;

        if (chunk < nchunk_full) {
            // 8 groups x 128 float4/array; each group front-batches 8 LDG.128
            const int g0 = base + lane;
            #pragma unroll
            for (int g = 0; g < 8; g++)
                fd_group_w(src, tgt, g0 + g * 128, acc0, acc1, acc2, acc3);
        } else {
            // partial tail chunk (n4 % WCHUNK_F4 != 0): bounds-checked
            for (int i = base + lane; i < n4; i += 32) {
                float4 b0 = src[i];
                float4 a0 = tgt[i];
                float u, s;
                u = (a0.x < 0.f && b0.x < 0.f) ? (b0.x - 2.f * a0.x) : b0.x;
                s = u * u;
                u = (a0.y < 0.f && b0.y < 0.f) ? (b0.y - 2.f * a0.y) : b0.y;
                s += u * u;
                u = (a0.z < 0.f && b0.z < 0.f) ? (b0.z - 2.f * a0.z) : b0.z;
                s += u * u;
                u = (a0.w < 0.f && b0.w < 0.f) ? (b0.w - 2.f * a0.w) : b0.w;
                s += u * u;
                acc0 += s;
            }
        }

        chunk = (int)__shfl_sync(0xFFFFFFFFu, nxt, 0);
    }

    // ---- epilogue: doubles only from here (off the memory-paced path) ----
    double acc = ((double)acc0 + (double)acc1) + ((double)acc2 + (double)acc3);

    #pragma unroll
    for (int off = 16; off > 0; off >>= 1)
        acc += __shfl_down_sync(0xFFFFFFFFu, acc, off);

    __shared__ double warp_sums[8];  // 256 threads = 8 warps
    if (lane == 0) warp_sums[wid] = acc;
    __syncthreads();  // all warps of the block are done streaming

    __shared__ bool is_last;
    if (t == 0) {
        double v = warp_sums[0];
        #pragma unroll
        for (int w = 1; w < 8; w++) v += warp_sums[w];
        atomicAdd(&g_fdloss_sum, v);
        __threadfence();
        unsigned int ticket = atomicInc(&g_fdloss_tick, gridDim.x - 1u);
        is_last = (ticket == gridDim.x - 1u);
    }
    __syncthreads();

    if (is_last && t == 0) {
        __threadfence();
        double s = g_fdloss_sum;
        out[0] = (float)(s * inv_n);
        g_fdloss_sum = 0.0;              // restore state for next replay
        atomicExch(&g_fdloss_work, 0u);  // restore work counter
    }
}

extern "C" void kernel_launch(void* const* d_in, const int* in_sizes, int n_in,
                              void* d_out, int out_size) {
    const float* src = (const float*)d_in[0];  // source -> b
    const float* tgt = (const float*)d_in[1];  // target -> a
    float* out = (float*)d_out;

    const long long n = (long long)in_sizes[0];
    const int n4 = (int)(n / 4);   // n = 51,380,224 -> n4 = 12,845,056

    const int nchunk_full  = n4 / WCHUNK_F4;                 // 12544 exact
    const int rem          = n4 - nchunk_full * WCHUNK_F4;   // 0 for this shape
    const int nchunk_total = nchunk_full + (rem ? 1 : 0);

    const int threads = 256;
    // One resident wave: 148 SMs x 6 CTAs/SM (~38 regs, 256 thr -> occ 6).
    int blocks = 148 * 6;
    long long max_blocks = ((long long)nchunk_total * 32 + threads - 1) / threads;
    if ((long long)blocks > max_blocks) blocks = (int)max_blocks;
    if (blocks < 1) blocks = 1;

    fdloss_kernel<<<blocks, threads>>>(
        (const float4*)src, (const float4*)tgt, n4,
        nchunk_total, nchunk_full, out, 1.0 / (double)n);
}